// round 11
// baseline (speedup 1.0000x reference)
#include <cuda_runtime.h>
#include <math.h>

// ---------------------------------------------------------------------------
// GRAPEIso: conv3x3(3->1024) + pixel_shuffle(4) + pixel_unshuffle(2) + head
// algebraically folded into a 96-output 3x3 conv, then Gaussian splatting.
// R11: raster rewritten scatter->GATHER: thread = pixel, no atomics at all.
// Membership test: pixel receives gaussian iff (cx-px)^2+(cy-py)^2 < ln(255)/2
// (this single test provably subsumes the 4x4 footprint bounds AND the
// reference's alpha>1/255 cutoff). 7x7 candidate window per pixel.
// Fixed shapes: B=4, inp 3x128x128, scale=2, grid 256x256 gaussians/batch,
// image 4x3x256x256 fp32 output.
// ---------------------------------------------------------------------------

#define BATCH   4
#define INH     128
#define INW     128
#define GH      256
#define GW      256
#define IMH     256
#define IMW     256
#define NGAUSS  (GH * GW)

#define TW      16
#define TH      16
#define RSX     22      // halo gaussians: gx in [tx0-2, tx0+19]
#define RSY     22

#define QCUT    2.7725887f   // ln(255)/2

__device__ __forceinline__ float tanh_approx(float x) {
    float r;
    asm("tanh.approx.f32 %0, %1;" : "=f"(r) : "f"(x));
    return r;
}

// Scratch (allocation-free contract: __device__ globals)
__device__ float  g_weff[4 * 27 * 24];          // [uv][t][o], o contiguous
__device__ float  g_beff[4 * 24];               // [uv][o]
__device__ float2 g_center[BATCH * NGAUSS];     // (cx, cy)
__device__ float4 g_color [BATCH * NGAUSS];     // (r, g, b, pad)

// ---------------------------------------------------------------------------
// Kernel 0: weight fold (v9 - at its measured ~6us floor).
// ---------------------------------------------------------------------------
__global__ void __launch_bounds__(512) fold_kernel(
    const float* __restrict__ w_enc,   // (1024, 3, 3, 3) -> [C*27 + t]
    const float* __restrict__ b_enc,   // (1024,)
    const float* __restrict__ w_head,  // (24, 256)
    const float* __restrict__ b_head)  // (24,)
{
    __shared__ float red[16][28];

    int uv = blockIdx.x / 24;          // grid 96
    int o  = blockIdx.x - uv * 24;
    int u = uv >> 1, v = uv & 1;

    int warp = threadIdx.x >> 5;
    int lane = threadIdx.x & 31;

    if (lane < 28) {
        float acc = 0.f;
        #pragma unroll
        for (int i = 0; i < 16; i++) {
            int ch = warp * 16 + i;
            int c = ch >> 2, a = (ch >> 1) & 1, e = ch & 1;
            int C = c * 16 + (2 * u + a) * 4 + (2 * v + e);
            float wh = __ldg(w_head + o * 256 + ch);           // warp-uniform
            float x  = (lane < 27) ? __ldg(w_enc + C * 27 + lane)
                                   : __ldg(b_enc + C);
            acc = fmaf(wh, x, acc);
        }
        red[warp][lane] = acc;
    }
    __syncthreads();

    if (threadIdx.x < 28) {
        int t = threadIdx.x;
        float s = 0.f;
        #pragma unroll
        for (int w = 0; w < 16; w++) s += red[w][t];
        if (t < 27) g_weff[uv * 648 + t * 24 + o] = s;
        else        g_beff[uv * 24 + o] = s + b_head[o];
    }
}

// ---------------------------------------------------------------------------
// Kernel 1: predict (frozen - the 41.5us config). 1024 CTAs x 64 threads.
// ---------------------------------------------------------------------------
__global__ void __launch_bounds__(64) predict_kernel(const float* __restrict__ inp)
{
    __shared__ __align__(16) float sW[4 * 648];      // [uv][t][o]
    __shared__ float sB[4 * 24];

    for (int i = threadIdx.x; i < 4 * 648; i += 64) sW[i] = g_weff[i];
    for (int i = threadIdx.x; i < 96; i += 64) sB[i] = g_beff[i];
    __syncthreads();

    int idx = blockIdx.x * 64 + threadIdx.x;    // 0..65535
    int b   = idx >> 14;
    int rem = idx & 16383;
    int i   = rem >> 7;
    int j   = rem & 127;

    float patch[27];
    const float* ib = inp + (size_t)b * 3 * INH * INW;
    #pragma unroll
    for (int ic = 0; ic < 3; ic++) {
        #pragma unroll
        for (int ky = 0; ky < 3; ky++) {
            int y = i + ky - 1;
            #pragma unroll
            for (int kx = 0; kx < 3; kx++) {
                int x = j + kx - 1;
                float vv = 0.f;
                if ((unsigned)y < INH && (unsigned)x < INW)
                    vv = __ldg(ib + ic * INH * INW + y * INW + x);
                patch[ic * 9 + ky * 3 + kx] = vv;
            }
        }
    }

    #pragma unroll
    for (int uv = 0; uv < 4; uv++) {
        float acc[24];
        #pragma unroll
        for (int o = 0; o < 24; o++) acc[o] = sB[uv * 24 + o];

        const float4* wrow = (const float4*)(sW + uv * 648);
        #pragma unroll
        for (int t = 0; t < 27; t++) {
            float xv = patch[t];
            #pragma unroll
            for (int q = 0; q < 6; q++) {
                float4 wv = wrow[t * 6 + q];
                acc[q * 4 + 0] = fmaf(wv.x, xv, acc[q * 4 + 0]);
                acc[q * 4 + 1] = fmaf(wv.y, xv, acc[q * 4 + 1]);
                acc[q * 4 + 2] = fmaf(wv.z, xv, acc[q * 4 + 2]);
                acc[q * 4 + 3] = fmaf(wv.w, xv, acc[q * 4 + 3]);
            }
        }

        float lg0 = acc[5], lg1 = acc[11], lg2 = acc[17], lg3 = acc[23];
        float m = fmaxf(fmaxf(lg0, lg1), fmaxf(lg2, lg3));
        float w0 = __expf(lg0 - m), w1 = __expf(lg1 - m);
        float w2 = __expf(lg2 - m), w3 = __expf(lg3 - m);
        float inv = 1.f / (w0 + w1 + w2 + w3);

        float r = 0.f, g = 0.f, bl = 0.f, ox = 0.f, oy = 0.f;
        #pragma unroll
        for (int k = 0; k < 4; k++) {
            float wk = ((k == 0) ? w0 : (k == 1) ? w1 : (k == 2) ? w2 : w3) * inv;
            r  = fmaf(acc[k * 6 + 0], wk, r);
            g  = fmaf(acc[k * 6 + 1], wk, g);
            bl = fmaf(acc[k * 6 + 2], wk, bl);
            ox = fmaf(tanh_approx(acc[k * 6 + 3]), wk, ox);
            oy = fmaf(tanh_approx(acc[k * 6 + 4]), wk, oy);
        }

        int u = uv >> 1, v = uv & 1;
        int gy = 2 * i + u, gx = 2 * j + v;
        float cx = (float)gx + 2.f * ox - 1.f;
        float cy = (float)gy + 2.f * oy - 1.f;

        int gidx = b * NGAUSS + gy * GW + gx;
        g_center[gidx] = make_float2(cx, cy);
        g_color[gidx]  = make_float4(r, g, bl, 0.f);
    }
}

// ---------------------------------------------------------------------------
// Kernel 2: rasterize, GATHER form. CTA = 16x16 tile, thread = pixel.
// Stage 22x22 halo gaussians (pos + color) in smem; each pixel scans its
// 7x7 candidate window with the single test q < ln(255)/2 (subsumes both
// footprint bounds and the alpha cutoff), accumulates rgb in registers.
// No atomics, no accumulator smem, one barrier, coalesced stores.
// ---------------------------------------------------------------------------
__global__ void __launch_bounds__(256) raster_kernel(float* __restrict__ out)
{
    __shared__ float2 sPos[RSY * RSX];   // 484 * 8B
    __shared__ float4 sCol[RSY * RSX];   // 484 * 16B

    int tx0 = (blockIdx.x & 15) * TW;
    int ty0 = (blockIdx.x >> 4) * TH;
    int b   = blockIdx.y;

    const float2* ctr = g_center + b * NGAUSS;
    const float4* col = g_color  + b * NGAUSS;

    for (int idx = threadIdx.x; idx < RSX * RSY; idx += 256) {
        int ry = idx / RSX, rx = idx - ry * RSX;
        int gy = ty0 - 2 + ry;
        int gx = tx0 - 2 + rx;
        float2 c  = make_float2(1e9f, 1e9f);     // sentinel: always rejected
        float4 cl = make_float4(0.f, 0.f, 0.f, 0.f);
        if ((unsigned)gy < GH && (unsigned)gx < GW) {
            int gi = gy * GW + gx;
            c  = ctr[gi];
            cl = col[gi];
        }
        sPos[idx] = c;
        sCol[idx] = cl;
    }
    __syncthreads();

    int tx = threadIdx.x & 15;
    int ty = threadIdx.x >> 4;
    float fpx = (float)(tx0 + tx);
    float fpy = (float)(ty0 + ty);

    float ar = 0.f, ag = 0.f, ab = 0.f;

    for (int dy = 0; dy < 7; dy++) {
        int rowbase = (ty + dy) * RSX + tx;
        #pragma unroll
        for (int dx = 0; dx < 7; dx++) {
            int gi = rowbase + dx;
            float2 c = sPos[gi];
            float ddx = c.x - fpx;
            float ddy = c.y - fpy;
            float q = fmaf(ddx, ddx, ddy * ddy);
            if (q < QCUT) {
                float a = fminf(__expf(-2.f * q), 0.999f);
                float4 cl = sCol[gi];
                ar = fmaf(a, cl.x, ar);
                ag = fmaf(a, cl.y, ag);
                ab = fmaf(a, cl.z, ab);
            }
        }
    }

    float* ob = out + (size_t)b * 3 * IMH * IMW;
    int o = (ty0 + ty) * IMW + (tx0 + tx);
    ob[o]                 = fminf(fmaxf(ar, 0.f), 1.f);
    ob[IMH * IMW + o]     = fminf(fmaxf(ag, 0.f), 1.f);
    ob[2 * IMH * IMW + o] = fminf(fmaxf(ab, 0.f), 1.f);
}

// ---------------------------------------------------------------------------
// Launch: fold -> predict -> raster, single stream, graph-capturable,
// no allocations anywhere (streams/events removed after R10 guard failure).
// Inputs (metadata order): inp, w_enc, b_enc, w_head, b_head, scale(unused)
// ---------------------------------------------------------------------------
extern "C" void kernel_launch(void* const* d_in, const int* in_sizes, int n_in,
                              void* d_out, int out_size)
{
    const float* inp    = (const float*)d_in[0];
    const float* w_enc  = (const float*)d_in[1];
    const float* b_enc  = (const float*)d_in[2];
    const float* w_head = (const float*)d_in[3];
    const float* b_head = (const float*)d_in[4];
    float* out = (float*)d_out;

    fold_kernel<<<96, 512>>>(w_enc, b_enc, w_head, b_head);
    predict_kernel<<<1024, 64>>>(inp);

    dim3 g(256, BATCH);
    raster_kernel<<<g, 256>>>(out);
}

// round 12
// speedup vs baseline: 1.1221x; 1.1221x over previous
#include <cuda_runtime.h>
#include <math.h>

// ---------------------------------------------------------------------------
// GRAPEIso: conv3x3(3->1024) + pixel_shuffle(4) + pixel_unshuffle(2) + head
// algebraically folded into a 96-output 3x3 conv, then Gaussian splatting
// with exclusive shared-memory image tiles (scatter + smem atomics; the R11
// gather variant measured 4.7us slower and 10x worse rel_err -> reverted).
// R12: PDL (programmatic dependent launch) on predict and raster so each
// successor's independent preamble (patch LDGs / smem zeroing) overlaps the
// predecessor's tail instead of waiting for full completion.
// Fixed shapes: B=4, inp 3x128x128, scale=2, grid 256x256 gaussians/batch,
// image 4x3x256x256 fp32 output.
// ---------------------------------------------------------------------------

#define BATCH   4
#define INH     128
#define INW     128
#define GH      256
#define GW      256
#define IMH     256
#define IMW     256
#define NGAUSS  (GH * GW)

#define TW      16
#define TH      16
#define RSX     22
#define RSY     22

__device__ __forceinline__ float tanh_approx(float x) {
    float r;
    asm("tanh.approx.f32 %0, %1;" : "=f"(r) : "f"(x));
    return r;
}

// Scratch (allocation-free contract: __device__ globals)
__device__ float  g_weff[4 * 27 * 24];          // [uv][t][o], o contiguous
__device__ float  g_beff[4 * 24];               // [uv][o]
__device__ float2 g_center[BATCH * NGAUSS];     // (cx, cy)
__device__ float4 g_color [BATCH * NGAUSS];     // (r, g, b, pad)

// ---------------------------------------------------------------------------
// Kernel 0: weight fold (v9 - measured floor ~6us across 5 variants).
// ---------------------------------------------------------------------------
__global__ void __launch_bounds__(512) fold_kernel(
    const float* __restrict__ w_enc,   // (1024, 3, 3, 3) -> [C*27 + t]
    const float* __restrict__ b_enc,   // (1024,)
    const float* __restrict__ w_head,  // (24, 256)
    const float* __restrict__ b_head)  // (24,)
{
    __shared__ float red[16][28];

    int uv = blockIdx.x / 24;          // grid 96
    int o  = blockIdx.x - uv * 24;
    int u = uv >> 1, v = uv & 1;

    int warp = threadIdx.x >> 5;
    int lane = threadIdx.x & 31;

    if (lane < 28) {
        float acc = 0.f;
        #pragma unroll
        for (int i = 0; i < 16; i++) {
            int ch = warp * 16 + i;
            int c = ch >> 2, a = (ch >> 1) & 1, e = ch & 1;
            int C = c * 16 + (2 * u + a) * 4 + (2 * v + e);
            float wh = __ldg(w_head + o * 256 + ch);           // warp-uniform
            float x  = (lane < 27) ? __ldg(w_enc + C * 27 + lane)
                                   : __ldg(b_enc + C);
            acc = fmaf(wh, x, acc);
        }
        red[warp][lane] = acc;
    }
    __syncthreads();

    if (threadIdx.x < 28) {
        int t = threadIdx.x;
        float s = 0.f;
        #pragma unroll
        for (int w = 0; w < 16; w++) s += red[w][t];
        if (t < 27) g_weff[uv * 648 + t * 24 + o] = s;
        else        g_beff[uv * 24 + o] = s + b_head[o];
    }
}

// ---------------------------------------------------------------------------
// Kernel 1: predict (frozen compute, R4 config). 1024 CTAs x 64 threads.
// PDL: patch LDGs issued BEFORE cudaGridDependencySynchronize(); weight
// staging (which needs fold's output) after it.
// ---------------------------------------------------------------------------
__global__ void __launch_bounds__(64) predict_kernel(const float* __restrict__ inp)
{
    __shared__ __align__(16) float sW[4 * 648];      // [uv][t][o]
    __shared__ float sB[4 * 24];

    int idx = blockIdx.x * 64 + threadIdx.x;    // 0..65535
    int b   = idx >> 14;
    int rem = idx & 16383;
    int i   = rem >> 7;
    int j   = rem & 127;

    // Patch loads first - independent of fold's output.
    float patch[27];
    const float* ib = inp + (size_t)b * 3 * INH * INW;
    #pragma unroll
    for (int ic = 0; ic < 3; ic++) {
        #pragma unroll
        for (int ky = 0; ky < 3; ky++) {
            int y = i + ky - 1;
            #pragma unroll
            for (int kx = 0; kx < 3; kx++) {
                int x = j + kx - 1;
                float vv = 0.f;
                if ((unsigned)y < INH && (unsigned)x < INW)
                    vv = __ldg(ib + ic * INH * INW + y * INW + x);
                patch[ic * 9 + ky * 3 + kx] = vv;
            }
        }
    }

    // Wait for fold's writes to be visible, then stage weights.
    cudaGridDependencySynchronize();

    for (int t = threadIdx.x; t < 4 * 648; t += 64) sW[t] = g_weff[t];
    for (int t = threadIdx.x; t < 96; t += 64) sB[t] = g_beff[t];
    __syncthreads();

    #pragma unroll
    for (int uv = 0; uv < 4; uv++) {
        float acc[24];
        #pragma unroll
        for (int o = 0; o < 24; o++) acc[o] = sB[uv * 24 + o];

        const float4* wrow = (const float4*)(sW + uv * 648);
        #pragma unroll
        for (int t = 0; t < 27; t++) {
            float xv = patch[t];
            #pragma unroll
            for (int q = 0; q < 6; q++) {
                float4 wv = wrow[t * 6 + q];
                acc[q * 4 + 0] = fmaf(wv.x, xv, acc[q * 4 + 0]);
                acc[q * 4 + 1] = fmaf(wv.y, xv, acc[q * 4 + 1]);
                acc[q * 4 + 2] = fmaf(wv.z, xv, acc[q * 4 + 2]);
                acc[q * 4 + 3] = fmaf(wv.w, xv, acc[q * 4 + 3]);
            }
        }

        float lg0 = acc[5], lg1 = acc[11], lg2 = acc[17], lg3 = acc[23];
        float m = fmaxf(fmaxf(lg0, lg1), fmaxf(lg2, lg3));
        float w0 = __expf(lg0 - m), w1 = __expf(lg1 - m);
        float w2 = __expf(lg2 - m), w3 = __expf(lg3 - m);
        float inv = 1.f / (w0 + w1 + w2 + w3);

        float r = 0.f, g = 0.f, bl = 0.f, ox = 0.f, oy = 0.f;
        #pragma unroll
        for (int k = 0; k < 4; k++) {
            float wk = ((k == 0) ? w0 : (k == 1) ? w1 : (k == 2) ? w2 : w3) * inv;
            r  = fmaf(acc[k * 6 + 0], wk, r);
            g  = fmaf(acc[k * 6 + 1], wk, g);
            bl = fmaf(acc[k * 6 + 2], wk, bl);
            ox = fmaf(tanh_approx(acc[k * 6 + 3]), wk, ox);
            oy = fmaf(tanh_approx(acc[k * 6 + 4]), wk, oy);
        }

        int u = uv >> 1, v = uv & 1;
        int gy = 2 * i + u, gx = 2 * j + v;
        float cx = (float)gx + 2.f * ox - 1.f;
        float cy = (float)gy + 2.f * oy - 1.f;

        int gidx = b * NGAUSS + gy * GW + gx;
        g_center[gidx] = make_float2(cx, cy);
        g_color[gidx]  = make_float4(r, g, bl, 0.f);
    }
}

// ---------------------------------------------------------------------------
// Kernel 2: rasterize, scatter form (R8 - the measured best). One CTA per
// 16x16 tile per batch; interleaved acc[3p+ch] (bank fix, ~3us win);
// 4x4 effective footprint; 22x22 halo; stride-5 lane permutation.
// PDL: smem zeroing before cudaGridDependencySynchronize().
// ---------------------------------------------------------------------------
__global__ void __launch_bounds__(256) raster_kernel(float* __restrict__ out)
{
    __shared__ float acc[3 * TH * TW];  // interleaved [p][ch]

    int tx0 = (blockIdx.x & 15) * TW;
    int ty0 = (blockIdx.x >> 4) * TH;
    int b   = blockIdx.y;

    for (int p = threadIdx.x; p < 3 * TH * TW; p += 256) acc[p] = 0.f;

    cudaGridDependencySynchronize();
    __syncthreads();

    const float2* ctr = g_center + b * NGAUSS;
    const float4* col = g_color  + b * NGAUSS;

    for (int idx = threadIdx.x; idx < RSX * RSY; idx += 256) {
        int ry = idx / RSX;
        int j  = idx - ry * RSX;
        int rx = (j * 5) % RSX;
        int gy = ty0 - 2 + ry;
        int gx = tx0 - 2 + rx;
        if ((unsigned)gy >= GH || (unsigned)gx >= GW) continue;

        int gi = gy * GW + gx;
        float2 c = ctr[gi];

        float ixf = floorf(c.x);
        float iyf = floorf(c.y);

        int txl = (int)ixf - 1 - tx0;
        int tyl = (int)iyf - 1 - ty0;
        if (txl >= TW || txl <= -4 || tyl >= TH || tyl <= -4) continue;

        float4 rgbv = col[gi];

        float ex[4], ey[4];
        #pragma unroll
        for (int o = 0; o < 4; o++) {
            float dx = ixf + (float)(o - 1) - c.x;
            float dy = iyf + (float)(o - 1) - c.y;
            ex[o] = __expf(-2.f * dx * dx);
            ey[o] = __expf(-2.f * dy * dy);
        }

        #pragma unroll
        for (int oy = 0; oy < 4; oy++) {
            int ty = tyl + oy;
            if ((unsigned)ty >= TH) continue;
            float eyv = ey[oy];
            #pragma unroll
            for (int ox = 0; ox < 4; ox++) {
                int tx = txl + ox;
                if ((unsigned)tx >= TW) continue;
                float a = fminf(eyv * ex[ox], 0.999f);
                if (a > (1.0f / 255.0f)) {
                    int p3 = (ty * TW + tx) * 3;
                    atomicAdd(&acc[p3 + 0], a * rgbv.x);
                    atomicAdd(&acc[p3 + 1], a * rgbv.y);
                    atomicAdd(&acc[p3 + 2], a * rgbv.z);
                }
            }
        }
    }
    __syncthreads();

    float* ob = out + (size_t)b * 3 * IMH * IMW;
    for (int p = threadIdx.x; p < TH * TW; p += 256) {
        int ty = p >> 4;
        int tx = p & 15;
        int o  = (ty0 + ty) * IMW + (tx0 + tx);
        #pragma unroll
        for (int ch = 0; ch < 3; ch++) {
            float vv = acc[p * 3 + ch];
            ob[ch * IMH * IMW + o] = fminf(fmaxf(vv, 0.f), 1.f);
        }
    }
}

// ---------------------------------------------------------------------------
// Launch: fold -> predict -> raster on ONE stream; predict and raster use
// programmatic stream serialization (PDL) so their preambles overlap the
// predecessor's tail. No streams/events/allocations (R10 guard lesson).
// Inputs (metadata order): inp, w_enc, b_enc, w_head, b_head, scale(unused)
// ---------------------------------------------------------------------------
extern "C" void kernel_launch(void* const* d_in, const int* in_sizes, int n_in,
                              void* d_out, int out_size)
{
    const float* inp    = (const float*)d_in[0];
    const float* w_enc  = (const float*)d_in[1];
    const float* b_enc  = (const float*)d_in[2];
    const float* w_head = (const float*)d_in[3];
    const float* b_head = (const float*)d_in[4];
    float* out = (float*)d_out;

    fold_kernel<<<96, 512>>>(w_enc, b_enc, w_head, b_head);

    cudaLaunchAttribute pdl[1];
    pdl[0].id = cudaLaunchAttributeProgrammaticStreamSerialization;
    pdl[0].val.programmaticStreamSerializationAllowed = 1;

    {
        cudaLaunchConfig_t cfg = {};
        cfg.gridDim  = dim3(1024);
        cfg.blockDim = dim3(64);
        cfg.attrs    = pdl;
        cfg.numAttrs = 1;
        if (cudaLaunchKernelEx(&cfg, predict_kernel, inp) != cudaSuccess)
            predict_kernel<<<1024, 64>>>(inp);
    }
    {
        cudaLaunchConfig_t cfg = {};
        cfg.gridDim  = dim3(256, BATCH);
        cfg.blockDim = dim3(256);
        cfg.attrs    = pdl;
        cfg.numAttrs = 1;
        if (cudaLaunchKernelEx(&cfg, raster_kernel, out) != cudaSuccess)
            raster_kernel<<<dim3(256, BATCH), 256>>>(out);
    }
}